// round 2
// baseline (speedup 1.0000x reference)
#include <cuda_runtime.h>

#define DIMD 128
#define MAXN 500352
#define MAXB 8192

// Scratch (no cudaMalloc allowed)
__device__ float g_dot[MAXN];       // dot_i, later exp_i (reused)
__device__ float g_a[DIMD];         // q_w^T k_w
__device__ float g_b[DIMD];         // q_w^T k_b
__device__ float g_c1, g_c2;        // q_b.k_w, q_b.k_b
__device__ float g_segmax[MAXB];
__device__ float g_segsum[MAXB];
__device__ int   g_is64;            // batch dtype flag

__device__ __forceinline__ int load_batch(const int* __restrict__ b32, int i, int is64) {
    // little-endian: low 32 bits of an int64 element i is at word index 2*i
    return b32[is64 ? (i << 1) : i];
}

__device__ __forceinline__ void atomicMaxFloat(float* addr, float v) {
    // init value must be -inf (0xFF800000)
    if (v >= 0.0f) atomicMax((int*)addr, __float_as_int(v));
    else           atomicMin((unsigned int*)addr, (unsigned int)__float_as_int(v));
}

// ---------------------------------------------------------------------------
// K0: fold weights, init segment tables, detect batch dtype
// ---------------------------------------------------------------------------
__global__ void k_pre(const float* __restrict__ qw, const float* __restrict__ qb,
                      const float* __restrict__ kw, const float* __restrict__ kb,
                      const int* __restrict__ bat32, int N, int B) {
    int t = blockIdx.x * blockDim.x + threadIdx.x;
    for (int i = t; i < B; i += gridDim.x * blockDim.x) {
        g_segmax[i] = __int_as_float(0xff800000);  // -inf
        g_segsum[i] = 0.0f;
    }
    if (blockIdx.x == 0) {
        int e = threadIdx.x;
        if (e < DIMD) {
            float sa = 0.0f, sb = 0.0f;
            #pragma unroll 8
            for (int d = 0; d < DIMD; d++) {
                float w = qw[d * DIMD + e];
                sa += w * kw[d];
                sb += w * kb[d];
            }
            g_a[e] = sa;
            g_b[e] = sb;
        } else if (e == DIMD) {
            float c1 = 0.0f, c2 = 0.0f;
            for (int d = 0; d < DIMD; d++) {
                c1 += qb[d] * kw[d];
                c2 += qb[d] * kb[d];
            }
            g_c1 = c1;
            g_c2 = c2;
        } else if (e == DIMD + 1) {
            // batch is SORTED, values in [0, B). If stored as int64, the 32-bit
            // word at an odd index is a high word == 0. If int32, a value at an
            // odd index near the end is ~B-1 != 0 (overwhelmingly likely).
            int j = ((N - 1) & 1) ? (N - 1) : (N - 3);
            if (j < 1) j = 1;
            g_is64 = (bat32[j] == 0) ? 1 : 0;
        }
    }
}

// ---------------------------------------------------------------------------
// K1: dot_i = (ele_b*(x.a + c1) + (x.b + c2)) / sqrt(D); seg max
// warp-per-row, float4 loads (one warp covers exactly 128 floats)
// ---------------------------------------------------------------------------
__global__ void k_dot(const float* __restrict__ x, const float* __restrict__ ele,
                      const int* __restrict__ bat32, int N) {
    __shared__ float4 sa[32], sb[32];
    if (threadIdx.x < 32)      sa[threadIdx.x]      = ((const float4*)g_a)[threadIdx.x];
    else if (threadIdx.x < 64) sb[threadIdx.x - 32] = ((const float4*)g_b)[threadIdx.x - 32];
    __syncthreads();

    const int   lane = threadIdx.x & 31;
    const int   warp = (blockIdx.x * blockDim.x + threadIdx.x) >> 5;
    const int   nw   = (gridDim.x * blockDim.x) >> 5;
    const int   is64 = g_is64;
    const float c1 = g_c1, c2 = g_c2;
    const float4 a4 = sa[lane];
    const float4 b4 = sb[lane];
    const float inv = 0.08838834764831845f;  // 1/sqrt(128)

    for (int r = warp; r < N; r += nw) {
        float4 xv = ((const float4*)x)[(size_t)r * 32 + lane];
        float s1 = xv.x * a4.x + xv.y * a4.y + xv.z * a4.z + xv.w * a4.w;
        float s2 = xv.x * b4.x + xv.y * b4.y + xv.z * b4.z + xv.w * b4.w;
        #pragma unroll
        for (int o = 16; o; o >>= 1) {
            s1 += __shfl_xor_sync(0xffffffff, s1, o);
            s2 += __shfl_xor_sync(0xffffffff, s2, o);
        }
        if (lane == 0) {
            int   b  = load_batch(bat32, r, is64);
            float el = __ldg(&ele[b]);
            float dot = (el * (s1 + c1) + (s2 + c2)) * inv;
            g_dot[r] = dot;
            atomicMaxFloat(&g_segmax[b], dot);
        }
    }
}

// ---------------------------------------------------------------------------
// K2: e_i = exp(dot_i - seg_max); seg sum
// ---------------------------------------------------------------------------
__global__ void k_exp(const int* __restrict__ bat32, int N) {
    const int is64 = g_is64;
    for (int i = blockIdx.x * blockDim.x + threadIdx.x; i < N;
         i += gridDim.x * blockDim.x) {
        int   b = load_batch(bat32, i, is64);
        float e = __expf(g_dot[i] - g_segmax[b]);
        g_dot[i] = e;
        atomicAdd(&g_segsum[b], e);
    }
}

// ---------------------------------------------------------------------------
// K3: out[i,:] = (e_i / (segsum + 1e-16)) * ele_b * v_w
// warp-per-row float4 stores
// ---------------------------------------------------------------------------
__global__ void k_out(const float* __restrict__ ele, const float* __restrict__ vw,
                      const int* __restrict__ bat32, float* __restrict__ out, int N) {
    const int lane = threadIdx.x & 31;
    const int warp = (blockIdx.x * blockDim.x + threadIdx.x) >> 5;
    const int nw   = (gridDim.x * blockDim.x) >> 5;
    const int is64 = g_is64;
    const float4 v4 = ((const float4*)vw)[lane];

    for (int r = warp; r < N; r += nw) {
        float coef;
        if (lane == 0) {
            int b = load_batch(bat32, r, is64);
            coef = g_dot[r] / (g_segsum[b] + 1e-16f) * __ldg(&ele[b]);
        }
        coef = __shfl_sync(0xffffffff, coef, 0);
        float4 o;
        o.x = v4.x * coef;
        o.y = v4.y * coef;
        o.z = v4.z * coef;
        o.w = v4.w * coef;
        ((float4*)out)[(size_t)r * 32 + lane] = o;
    }
}

// ---------------------------------------------------------------------------
extern "C" void kernel_launch(void* const* d_in, const int* in_sizes, int n_in,
                              void* d_out, int out_size) {
    if (n_in < 8 || !d_in || !d_out) return;

    const float* x   = (const float*)d_in[0];   // [N,128]
    const float* ele = (const float*)d_in[1];   // [B]
    const float* qw  = (const float*)d_in[2];   // [128,128]
    const float* qb  = (const float*)d_in[3];   // [128]
    const float* kw  = (const float*)d_in[4];   // [128] (D,1)
    const float* kb  = (const float*)d_in[5];   // [128]
    const float* vw  = (const float*)d_in[6];   // [128] (D,1)
    const int*   bat = (const int*)d_in[7];     // [N] int32 or int64 (auto-detected)
    float* out = (float*)d_out;

    int N = in_sizes[0] / DIMD;
    int Nout = out_size / DIMD;          // cross-check: out is [N,128]
    if (Nout > 0 && Nout < N) N = Nout;  // never store past d_out
    int B = in_sizes[1];
    if (N > MAXN) N = MAXN;   // scratch capacity (problem-fixed N=500000)
    if (B > MAXB) B = MAXB;
    if (N <= 0 || B <= 0) return;

    k_pre<<<16, 256>>>(qw, qb, kw, kb, bat, N, B);
    k_dot<<<2048, 256>>>(x, ele, bat, N);
    k_exp<<<1024, 256>>>(bat, N);
    k_out<<<2048, 256>>>(ele, vw, bat, out, N);
}

// round 4
// speedup vs baseline: 1.5835x; 1.5835x over previous
#include <cuda_runtime.h>

#define DIMD 128
#define MAXN 500352
#define MAXB 8192

// Scratch (no cudaMalloc allowed)
__device__ float g_dot[MAXN];       // dot_i, later exp_i (reused)
__device__ float g_a[DIMD];         // q_w^T k_w
__device__ float g_b[DIMD];         // q_w^T k_b
__device__ float g_c1, g_c2;        // q_b.k_w, q_b.k_b
__device__ float g_segmax[MAXB];
__device__ float g_segsum[MAXB];
__device__ int   g_is64;            // batch dtype flag

__device__ __forceinline__ int load_batch(const int* __restrict__ b32, int i, int is64) {
    // little-endian: low 32 bits of an int64 element i is at word index 2*i
    return b32[is64 ? (i << 1) : i];
}

__device__ __forceinline__ void atomicMaxFloat(float* addr, float v) {
    // init value must be -inf (0xFF800000)
    if (v >= 0.0f) atomicMax((int*)addr, __float_as_int(v));
    else           atomicMin((unsigned int*)addr, (unsigned int)__float_as_int(v));
}

// ---------------------------------------------------------------------------
// K0: fold weights, init segment tables, detect batch dtype
// ---------------------------------------------------------------------------
__global__ void k_pre(const float* __restrict__ qw, const float* __restrict__ qb,
                      const float* __restrict__ kw, const float* __restrict__ kb,
                      const int* __restrict__ bat32, int N, int B) {
    int t = blockIdx.x * blockDim.x + threadIdx.x;
    for (int i = t; i < B; i += gridDim.x * blockDim.x) {
        g_segmax[i] = __int_as_float(0xff800000);  // -inf
        g_segsum[i] = 0.0f;
    }
    if (blockIdx.x == 0) {
        int e = threadIdx.x;
        if (e < DIMD) {
            float sa = 0.0f, sb = 0.0f;
            #pragma unroll 8
            for (int d = 0; d < DIMD; d++) {
                float w = qw[d * DIMD + e];
                sa += w * kw[d];
                sb += w * kb[d];
            }
            g_a[e] = sa;
            g_b[e] = sb;
        } else if (e == DIMD) {
            float c1 = 0.0f, c2 = 0.0f;
            for (int d = 0; d < DIMD; d++) {
                c1 += qb[d] * kw[d];
                c2 += qb[d] * kb[d];
            }
            g_c1 = c1;
            g_c2 = c2;
        } else if (e == DIMD + 1) {
            // batch is SORTED, values in [0, B). If stored as int64, the 32-bit
            // word at an odd index is a high word == 0. If int32, a value at an
            // odd index near the end is ~B-1 != 0.
            int j = ((N - 1) & 1) ? (N - 1) : (N - 3);
            if (j < 1) j = 1;
            g_is64 = (bat32[j] == 0) ? 1 : 0;
        }
    }
}

// ---------------------------------------------------------------------------
// K1: dot_i = (ele_b*(x.a + c1) + (x.b + c2)) / sqrt(D); seg max
// Warp processes 4 rows per iteration for MLP; epilogue spread over lanes 0-3.
// ---------------------------------------------------------------------------
__global__ void k_dot(const float* __restrict__ x, const float* __restrict__ ele,
                      const int* __restrict__ bat32, int N) {
    __shared__ float4 sa[32], sb[32];
    if (threadIdx.x < 32)      sa[threadIdx.x]      = ((const float4*)g_a)[threadIdx.x];
    else if (threadIdx.x < 64) sb[threadIdx.x - 32] = ((const float4*)g_b)[threadIdx.x - 32];
    __syncthreads();

    const int   lane = threadIdx.x & 31;
    const int   warp = (blockIdx.x * blockDim.x + threadIdx.x) >> 5;
    const int   nw   = (gridDim.x * blockDim.x) >> 5;
    const int   is64 = g_is64;
    const float c1 = g_c1, c2 = g_c2;
    const float4 a4 = sa[lane];
    const float4 b4 = sb[lane];
    const float inv = 0.08838834764831845f;  // 1/sqrt(128)
    const int ntiles = (N + 3) >> 2;

    for (int t = warp; t < ntiles; t += nw) {
        const int r0 = t << 2;
        float s1[4], s2[4];
        #pragma unroll
        for (int j = 0; j < 4; j++) {
            if (r0 + j < N) {
                float4 xv = ((const float4*)x)[(size_t)(r0 + j) * 32 + lane];
                s1[j] = xv.x * a4.x + xv.y * a4.y + xv.z * a4.z + xv.w * a4.w;
                s2[j] = xv.x * b4.x + xv.y * b4.y + xv.z * b4.z + xv.w * b4.w;
            } else { s1[j] = 0.0f; s2[j] = 0.0f; }
        }
        #pragma unroll
        for (int o = 16; o; o >>= 1) {
            #pragma unroll
            for (int j = 0; j < 4; j++) {
                s1[j] += __shfl_xor_sync(0xffffffff, s1[j], o);
                s2[j] += __shfl_xor_sync(0xffffffff, s2[j], o);
            }
        }
        // After the butterfly every lane holds the full sums for all 4 rows.
        // Lanes 0..3 each finish one row: 4 parallel epilogue chains.
        if (lane < 4) {
            int r = r0 + lane;
            if (r < N) {
                float v1 = s1[lane];
                float v2 = s2[lane];
                int   b  = load_batch(bat32, r, is64);
                float el = __ldg(&ele[b]);
                float dot = (el * (v1 + c1) + (v2 + c2)) * inv;
                g_dot[r] = dot;
                atomicMaxFloat(&g_segmax[b], dot);
            }
        }
    }
}

// ---------------------------------------------------------------------------
// K2: e_i = exp(dot_i - seg_max); seg sum with warp-aggregated atomics
// (batch is sorted => most warps are segment-uniform)
// ---------------------------------------------------------------------------
__global__ void k_exp(const int* __restrict__ bat32, int N) {
    const int is64   = g_is64;
    const int lane   = threadIdx.x & 31;
    const int stride = gridDim.x * blockDim.x;
    const int tid    = blockIdx.x * blockDim.x + threadIdx.x;
    const int iters  = (N + stride - 1) / stride;   // uniform trip count

    for (int k = 0; k < iters; k++) {
        int  i     = tid + k * stride;
        bool valid = (i < N);
        int   b = valid ? load_batch(bat32, i, is64) : -1;
        float e = 0.0f;
        if (valid) {
            e = __expf(g_dot[i] - g_segmax[b]);
            g_dot[i] = e;
        }
        int b0 = __shfl_sync(0xffffffff, b, 0);
        if (__all_sync(0xffffffff, b == b0)) {
            // uniform segment: one atomic per warp
            #pragma unroll
            for (int o = 16; o; o >>= 1) e += __shfl_xor_sync(0xffffffff, e, o);
            if (lane == 0 && b0 >= 0) atomicAdd(&g_segsum[b0], e);
        } else {
            if (valid) atomicAdd(&g_segsum[b], e);
        }
    }
}

// ---------------------------------------------------------------------------
// K3: out[i,:] = (e_i / (segsum + 1e-16)) * ele_b * v_w
// Warp tiles 32 rows: parallel coef gather (MLP=32), then 32 indep STG.128/lane.
// ---------------------------------------------------------------------------
__global__ void k_out(const float* __restrict__ ele, const float* __restrict__ vw,
                      const int* __restrict__ bat32, float* __restrict__ out, int N) {
    const int lane = threadIdx.x & 31;
    const int warp = (blockIdx.x * blockDim.x + threadIdx.x) >> 5;
    const int nw   = (gridDim.x * blockDim.x) >> 5;
    const int is64 = g_is64;
    const float4 v4 = ((const float4*)vw)[lane];
    const int ntiles = (N + 31) >> 5;

    for (int t = warp; t < ntiles; t += nw) {
        const int r0 = t << 5;
        const int r  = r0 + lane;
        float coef = 0.0f;
        if (r < N) {
            int b = load_batch(bat32, r, is64);
            coef = g_dot[r] / (g_segsum[b] + 1e-16f) * __ldg(&ele[b]);
        }
        const int nr = min(32, N - r0);
        float4* dst = ((float4*)out) + (size_t)r0 * 32 + lane;
        #pragma unroll 8
        for (int c = 0; c < nr; c++) {
            float cf = __shfl_sync(0xffffffff, coef, c);
            dst[(size_t)c * 32] = make_float4(v4.x * cf, v4.y * cf, v4.z * cf, v4.w * cf);
        }
    }
}

// ---------------------------------------------------------------------------
extern "C" void kernel_launch(void* const* d_in, const int* in_sizes, int n_in,
                              void* d_out, int out_size) {
    if (n_in < 8 || !d_in || !d_out) return;

    const float* x   = (const float*)d_in[0];   // [N,128]
    const float* ele = (const float*)d_in[1];   // [B]
    const float* qw  = (const float*)d_in[2];   // [128,128]
    const float* qb  = (const float*)d_in[3];   // [128]
    const float* kw  = (const float*)d_in[4];   // [128] (D,1)
    const float* kb  = (const float*)d_in[5];   // [128]
    const float* vw  = (const float*)d_in[6];   // [128] (D,1)
    const int*   bat = (const int*)d_in[7];     // [N] int32 or int64 (auto-detected)
    float* out = (float*)d_out;

    int N = in_sizes[0] / DIMD;
    int Nout = out_size / DIMD;          // cross-check: out is [N,128]
    if (Nout > 0 && Nout < N) N = Nout;  // never store past d_out
    int B = in_sizes[1];
    if (N > MAXN) N = MAXN;   // scratch capacity (problem-fixed N=500000)
    if (B > MAXB) B = MAXB;
    if (N <= 0 || B <= 0) return;

    k_pre<<<16, 256>>>(qw, qb, kw, kb, bat, N, B);
    k_dot<<<2048, 256>>>(x, ele, bat, N);
    k_exp<<<1024, 256>>>(bat, N);
    k_out<<<2048, 256>>>(ele, vw, bat, out, N);
}